// round 2
// baseline (speedup 1.0000x reference)
#include <cuda_runtime.h>
#include <math.h>

#define NN 50000
#define EE 800000

// ---------------- scratch (device globals; no allocations allowed) ----------
__device__ float g_y[NN * 64];      // messages y = h @ Wl^T
__device__ float g_r[NN * 64];      // root    r = h @ Wr^T
__device__ float g_h[NN * 64];      // pre-BN hidden
__device__ float g_stats[128];      // per-channel sum / sumsq
__device__ float g_ab[256];         // BN affine: [a1|c1|a2|c2]
__device__ float g_P[NN * 128];     // P = hf @ Wm1[:, :64]^T + bm1
__device__ float g_Q[NN * 128];     // Q = hf @ Wm1[:, 80:]^T
__device__ int   g_deg[NN];         // in-degree
__device__ int   g_off[NN + 1];     // CSR offsets
__device__ int   g_fill[NN];        // fill cursors
__device__ int   g_csr[EE];         // src node per CSR slot (sorted by dst)
__device__ int   g_idx64;           // 1 if edge_index is int64, 0 if int32

// ---------------- packed f32x2 helpers (Blackwell FFMA2 path) ---------------
__device__ __forceinline__ unsigned long long fma_x2(
    unsigned long long a, unsigned long long b, unsigned long long c) {
    unsigned long long d;
    asm("fma.rn.f32x2 %0, %1, %2, %3;" : "=l"(d) : "l"(a), "l"(b), "l"(c));
    return d;
}
__device__ __forceinline__ unsigned long long pack2(float a, float b) {
    unsigned long long d;
    asm("mov.b64 %0, {%1, %2};" : "=l"(d) : "f"(a), "f"(b));
    return d;
}
__device__ __forceinline__ float2 unpack2(unsigned long long v) {
    float2 r;
    asm("mov.b64 {%0, %1}, %2;" : "=f"(r.x), "=f"(r.y) : "l"(v));
    return r;
}

// ---------------- dtype detection for edge_index ---------------------------
__global__ void detect_idx_kernel(const void* ei) {
    const unsigned int* w = (const unsigned int*)ei;
    int f = 1;
    for (int i = 0; i < 32; i++)
        if (w[2 * i + 1] != 0u) f = 0;   // int32 data: odd words are random ids
    g_idx64 = f;
}

__device__ __forceinline__ int load_idx(const void* ei, long long i, int is64) {
    if (is64) return (int)__ldg(((const long long*)ei) + i);
    return __ldg(((const int*)ei) + i);
}

// ---------------- CSR build --------------------------------------------------
__global__ void hist_kernel(const void* __restrict__ ei, int* __restrict__ deg) {
    int e = blockIdx.x * blockDim.x + threadIdx.x;
    if (e >= EE) return;
    int dst = load_idx(ei, (long long)EE + e, g_idx64);
    atomicAdd(deg + dst, 1);
}

__global__ void scan_kernel(const int* __restrict__ deg, int* __restrict__ off) {
    __shared__ int part[1024];
    int tid = threadIdx.x;                 // 1024 threads, 1 block
    const int CH = (NN + 1023) / 1024;     // 49
    int s0 = tid * CH;
    int lsum = 0;
    for (int i = 0; i < CH; i++) {
        int idx = s0 + i;
        if (idx < NN) lsum += deg[idx];
    }
    part[tid] = lsum;
    __syncthreads();
    for (int d = 1; d < 1024; d <<= 1) {
        int v = (tid >= d) ? part[tid - d] : 0;
        __syncthreads();
        part[tid] += v;
        __syncthreads();
    }
    int run = (tid == 0) ? 0 : part[tid - 1];
    for (int i = 0; i < CH; i++) {
        int idx = s0 + i;
        if (idx < NN) { off[idx] = run; run += deg[idx]; }
    }
    if (tid == 1023) off[NN] = run;
}

__global__ void csr_fill_kernel(const void* __restrict__ ei,
                                const int* __restrict__ off,
                                int* __restrict__ fill,
                                int* __restrict__ csr) {
    int e = blockIdx.x * blockDim.x + threadIdx.x;
    if (e >= EE) return;
    int is64 = g_idx64;
    int src = load_idx(ei, e, is64);
    int dst = load_idx(ei, (long long)EE + e, is64);
    int slot = off[dst] + atomicAdd(fill + dst, 1);
    csr[slot] = src;
}

// ---------------- aggregate + finalize + BN stats (fused) --------------------
// h[n] = mean_{src->n} y[src] + bl + r[n]; stats <- per-channel sum/sumsq
__global__ void aggregate_kernel(const int* __restrict__ off,
                                 const int* __restrict__ csr,
                                 const float* __restrict__ y,
                                 const float* __restrict__ r,
                                 const float* __restrict__ bl,
                                 float* __restrict__ h,
                                 float* __restrict__ stats) {
    __shared__ float sbuf[128];
    int tid = threadIdx.x;
    int lane = tid & 31, wid = tid >> 5;
    if (tid < 128) sbuf[tid] = 0.f;
    __syncthreads();

    int n = blockIdx.x * 8 + wid;          // 8 warps = 8 nodes per block
    int beg = off[n], end = off[n + 1];
    float2 acc = make_float2(0.f, 0.f);
    for (int base = beg; base < end; base += 32) {
        int idx = base + lane;
        int s = (idx < end) ? __ldg(csr + idx) : 0;
        int m = min(32, end - base);
        for (int j = 0; j < m; j++) {
            int sj = __shfl_sync(0xffffffffu, s, j);
            float2 v = *(const float2*)(y + (size_t)sj * 64 + lane * 2);
            acc.x += v.x;
            acc.y += v.y;
        }
    }
    int c = lane * 2;
    float inv = 1.f / fmaxf((float)(end - beg), 1.f);
    float2 rv = *(const float2*)(r + (size_t)n * 64 + c);
    float h0 = acc.x * inv + __ldg(bl + c) + rv.x;
    float h1 = acc.y * inv + __ldg(bl + c + 1) + rv.y;
    float2 hv = make_float2(h0, h1);
    *(float2*)(h + (size_t)n * 64 + c) = hv;
    atomicAdd(&sbuf[c], h0);
    atomicAdd(&sbuf[c + 1], h1);
    atomicAdd(&sbuf[64 + c], h0 * h0);
    atomicAdd(&sbuf[64 + c + 1], h1 * h1);
    __syncthreads();
    if (tid < 128) atomicAdd(stats + tid, sbuf[tid]);
}

// ---------------- BN params: a = g/sqrt(var+eps), c = beta - a*mu ------------
__global__ void bn_param_kernel(const float* __restrict__ stats,
                                const float* __restrict__ gamma,
                                const float* __restrict__ beta,
                                float* __restrict__ ab) {
    int c = threadIdx.x;  // 64 threads
    float mu = stats[c] * (1.f / (float)NN);
    float var = stats[64 + c] * (1.f / (float)NN) - mu * mu;
    float a = gamma[c] * rsqrtf(var + 1e-5f);
    ab[c] = a;
    ab[64 + c] = beta[c] - a * mu;
}

// ---------------- node GEMM (FFMA2, k-pair interleaved smem) -----------------
// out[n, o] = sum_k A[n,k] * Brow(o)[k]. Columns < split from B1/out1
// (optional bias1), else B2/out2. Optional fused BN affine+ReLU on A load.
template <int K>
__global__ void __launch_bounds__(256, 2) node_gemm(
    const float* __restrict__ A,
    const float* __restrict__ B1, int ldb1,
    const float* __restrict__ B2, int ldb2,
    int split,
    float* __restrict__ out1, int w1, const float* __restrict__ bias1,
    float* __restrict__ out2, int w2,
    const float* __restrict__ ab) {
    extern __shared__ float sm[];
    const int PR = K / 2;
    float* As = sm;                 // [PR][136]: As[p*136 + n*2 + parity]
    float* Bs = sm + PR * 136;      // [PR][256]: Bs[p*256 + o*2 + parity]
    const int tid = threadIdx.x;
    const int colBase = blockIdx.y * 128;

    // stage B (once per block), k-pair interleaved
    {
        int o = tid & 127;
        int colg = colBase + o;
        const float* brow = (colg < split) ? (B1 + (size_t)colg * ldb1)
                                           : (B2 + (size_t)(colg - split) * ldb2);
        for (int k = (tid >> 7); k < K; k += 2)
            Bs[(k >> 1) * 256 + o * 2 + (k & 1)] = __ldg(brow + k);
    }
    __syncthreads();

    const int tx = tid & 15;   // output group (8 cols)
    const int ty = tid >> 4;   // node group (4 rows)

    float binit[8];
#pragma unroll
    for (int j = 0; j < 8; j++) {
        int colg = colBase + tx * 8 + j;
        binit[j] = (bias1 != nullptr && colg < split) ? __ldg(bias1 + colg) : 0.f;
    }

    const int numTiles = (NN + 63) / 64;
    for (int nt = blockIdx.x; nt < numTiles; nt += gridDim.x) {
        int n0 = nt * 64;
        // stage A tile, k-pair interleaved, optional fused BN+ReLU
        {
            int nl = tid >> 2;
            int n = n0 + nl;
            int kq = (tid & 3) * 4;
#pragma unroll
            for (int kb = kq; kb < K; kb += 16) {
                float4 v;
                if (n < NN) v = *(const float4*)(A + (size_t)n * K + kb);
                else        v = make_float4(0.f, 0.f, 0.f, 0.f);
                if (ab) {
                    v.x = fmaxf(ab[kb + 0] * v.x + ab[64 + kb + 0], 0.f);
                    v.y = fmaxf(ab[kb + 1] * v.y + ab[64 + kb + 1], 0.f);
                    v.z = fmaxf(ab[kb + 2] * v.z + ab[64 + kb + 2], 0.f);
                    v.w = fmaxf(ab[kb + 3] * v.w + ab[64 + kb + 3], 0.f);
                }
                int p0 = kb >> 1;          // kb is multiple of 4
                As[p0 * 136 + nl * 2 + 0] = v.x;
                As[p0 * 136 + nl * 2 + 1] = v.y;
                As[(p0 + 1) * 136 + nl * 2 + 0] = v.z;
                As[(p0 + 1) * 136 + nl * 2 + 1] = v.w;
            }
        }
        __syncthreads();

        unsigned long long acc[4][8];
#pragma unroll
        for (int i = 0; i < 4; i++)
#pragma unroll
            for (int j = 0; j < 8; j++) acc[i][j] = 0ull;

#pragma unroll 2
        for (int p = 0; p < PR; p++) {
            ulonglong2 a01 = *(const ulonglong2*)(As + p * 136 + ty * 8);
            ulonglong2 a23 = *(const ulonglong2*)(As + p * 136 + ty * 8 + 4);
            ulonglong2 b01 = *(const ulonglong2*)(Bs + p * 256 + tx * 16);
            ulonglong2 b23 = *(const ulonglong2*)(Bs + p * 256 + tx * 16 + 4);
            ulonglong2 b45 = *(const ulonglong2*)(Bs + p * 256 + tx * 16 + 8);
            ulonglong2 b67 = *(const ulonglong2*)(Bs + p * 256 + tx * 16 + 12);
            unsigned long long av[4] = {a01.x, a01.y, a23.x, a23.y};
            unsigned long long bv[8] = {b01.x, b01.y, b23.x, b23.y,
                                        b45.x, b45.y, b67.x, b67.y};
#pragma unroll
            for (int i = 0; i < 4; i++)
#pragma unroll
                for (int j = 0; j < 8; j++)
                    acc[i][j] = fma_x2(av[i], bv[j], acc[i][j]);
        }
        __syncthreads();

        int colg0 = colBase + tx * 8;
#pragma unroll
        for (int i = 0; i < 4; i++) {
            int n = n0 + ty * 4 + i;
            if (n < NN) {
                float res[8];
#pragma unroll
                for (int j = 0; j < 8; j++) {
                    float2 t = unpack2(acc[i][j]);
                    res[j] = t.x + t.y + binit[j];
                }
                float4 v0 = make_float4(res[0], res[1], res[2], res[3]);
                float4 v1 = make_float4(res[4], res[5], res[6], res[7]);
                if (colg0 < split) {
                    *(float4*)(out1 + (size_t)n * w1 + colg0) = v0;
                    *(float4*)(out1 + (size_t)n * w1 + colg0 + 4) = v1;
                } else {
                    *(float4*)(out2 + (size_t)n * w2 + colg0 - split) = v0;
                    *(float4*)(out2 + (size_t)n * w2 + colg0 - split + 4) = v1;
                }
            }
        }
    }
}

// ---------------- per-edge MLP (FFMA2 everywhere) ----------------------------
// z1 = relu(P[src] + Q[dst] + ea @ Wm1e^T)     (P already carries bm1)
// z2 = relu(z1 @ Wm2^T + bm2);  out = z2 @ Wm3^T + bm3
__global__ void __launch_bounds__(256, 2) edge_mlp_kernel(
    const void* __restrict__ ei, const float* __restrict__ ea,
    const float* __restrict__ P, const float* __restrict__ Q,
    const float* __restrict__ Wm1, const float* __restrict__ Wm2,
    const float* __restrict__ bm2, const float* __restrict__ Wm3,
    const float* __restrict__ bm3, float* __restrict__ out) {
    extern __shared__ float sm[];
    float* z1s  = sm;                 // [p:64][e:128 x 2 +pad] -> stride 264
    float* w2s  = z1s + 64 * 264;     // [p:64][o:64 x 2]: w2s[p*128 + o*2 + par]
    float* w1es = w2s + 64 * 128;     // [k:16][j:128]
    float* w3s  = w1es + 16 * 128;    // [c:64][2]
    float* bm2s = w3s + 128;          // [64]
    int tid = threadIdx.x;
    int is64 = g_idx64;

    for (int i = tid; i < 64 * 128; i += 256) {
        int o = i >> 7, k = i & 127;
        w2s[(k >> 1) * 128 + o * 2 + (k & 1)] = __ldg(Wm2 + o * 128 + k);
    }
    for (int i = tid; i < 16 * 128; i += 256) {
        int j = i >> 4, k = i & 15;
        w1es[k * 128 + j] = __ldg(Wm1 + j * 144 + 64 + k);
    }
    if (tid < 128) { int c2 = tid >> 1, t = tid & 1; w3s[tid] = __ldg(Wm3 + t * 64 + c2); }
    if (tid < 64) bm2s[tid] = __ldg(bm2 + tid);
    __syncthreads();

    // ---- phase A: build z1 tile (one warp per edge), packed j-pairs ----
    int warp = tid >> 5, lane = tid & 31;
    int e0 = blockIdx.x * 128;
    for (int el = warp; el < 128; el += 8) {
        int e = e0 + el;
        float2 r01 = make_float2(0.f, 0.f), r23 = make_float2(0.f, 0.f);
        if (e < EE) {
            int src = load_idx(ei, e, is64);
            int dst = load_idx(ei, (long long)EE + e, is64);
            float4 p = *(const float4*)(P + (size_t)src * 128 + lane * 4);
            float4 q = *(const float4*)(Q + (size_t)dst * 128 + lane * 4);
            unsigned long long a01 = pack2(p.x + q.x, p.y + q.y);
            unsigned long long a23 = pack2(p.z + q.z, p.w + q.w);
            float v = (lane < 16) ? __ldg(ea + (size_t)e * 16 + lane) : 0.f;
#pragma unroll
            for (int k = 0; k < 16; k++) {
                float sc = __shfl_sync(0xffffffffu, v, k);
                unsigned long long scp = pack2(sc, sc);
                ulonglong2 wv = *(const ulonglong2*)(w1es + k * 128 + lane * 4);
                a01 = fma_x2(scp, wv.x, a01);
                a23 = fma_x2(scp, wv.y, a23);
            }
            float2 t01 = unpack2(a01), t23 = unpack2(a23);
            r01.x = fmaxf(t01.x, 0.f); r01.y = fmaxf(t01.y, 0.f);
            r23.x = fmaxf(t23.x, 0.f); r23.y = fmaxf(t23.y, 0.f);
        }
        // channel c = lane*4 + t -> pair p = 2*lane + (t>>1), parity = t&1
        *(float2*)(z1s + (2 * lane) * 264 + el * 2) = r01;
        *(float2*)(z1s + (2 * lane + 1) * 264 + el * 2) = r23;
    }
    __syncthreads();

    // ---- phase B: GEMM2 with FFMA2, 128 edges x 64 outs, reg tile 4x8 ----
    int og = tid & 7;    // 8 output groups of 8
    int eg = tid >> 3;   // 32 edge groups of 4
    unsigned long long acc2[4][8];
#pragma unroll
    for (int i = 0; i < 4; i++)
#pragma unroll
        for (int j = 0; j < 8; j++) acc2[i][j] = 0ull;

#pragma unroll 2
    for (int p = 0; p < 64; p++) {
        ulonglong2 a01 = *(const ulonglong2*)(z1s + p * 264 + eg * 8);
        ulonglong2 a23 = *(const ulonglong2*)(z1s + p * 264 + eg * 8 + 4);
        ulonglong2 b01 = *(const ulonglong2*)(w2s + p * 128 + og * 16);
        ulonglong2 b23 = *(const ulonglong2*)(w2s + p * 128 + og * 16 + 4);
        ulonglong2 b45 = *(const ulonglong2*)(w2s + p * 128 + og * 16 + 8);
        ulonglong2 b67 = *(const ulonglong2*)(w2s + p * 128 + og * 16 + 12);
        unsigned long long av[4] = {a01.x, a01.y, a23.x, a23.y};
        unsigned long long bv[8] = {b01.x, b01.y, b23.x, b23.y,
                                    b45.x, b45.y, b67.x, b67.y};
#pragma unroll
        for (int i = 0; i < 4; i++)
#pragma unroll
            for (int j = 0; j < 8; j++)
                acc2[i][j] = fma_x2(av[i], bv[j], acc2[i][j]);
    }

    // ---- phase C: bias + relu + layer3 partial dot, reduce over 8 lanes ----
    float o0[4] = {0.f, 0.f, 0.f, 0.f};
    float o1[4] = {0.f, 0.f, 0.f, 0.f};
#pragma unroll
    for (int j = 0; j < 8; j++) {
        int ch = og * 8 + j;
        float w30 = w3s[ch * 2], w31 = w3s[ch * 2 + 1], bb = bm2s[ch];
#pragma unroll
        for (int i = 0; i < 4; i++) {
            float2 t = unpack2(acc2[i][j]);
            float z = fmaxf(t.x + t.y + bb, 0.f);
            o0[i] += z * w30;
            o1[i] += z * w31;
        }
    }
#pragma unroll
    for (int i = 0; i < 4; i++) {
#pragma unroll
        for (int off = 4; off > 0; off >>= 1) {
            o0[i] += __shfl_down_sync(0xffffffffu, o0[i], off, 8);
            o1[i] += __shfl_down_sync(0xffffffffu, o1[i], off, 8);
        }
    }
    if (og == 0) {
        float b30 = __ldg(bm3), b31 = __ldg(bm3 + 1);
#pragma unroll
        for (int i = 0; i < 4; i++) {
            int e = e0 + eg * 4 + i;
            if (e < EE) {
                float2 rv;
                rv.x = o0[i] + b30;
                rv.y = o1[i] + b31;
                *(float2*)(out + (size_t)e * 2) = rv;
            }
        }
    }
}

// ---------------- host orchestration ----------------------------------------
extern "C" void kernel_launch(void* const* d_in, const int* in_sizes, int n_in,
                              void* d_out, int out_size) {
    (void)in_sizes; (void)n_in; (void)out_size;
    const float* x   = (const float*)d_in[0];
    const void*  ei  = d_in[1];
    const float* ea  = (const float*)d_in[2];
    const float* W1l = (const float*)d_in[3];
    const float* b1l = (const float*)d_in[4];
    const float* W1r = (const float*)d_in[5];
    const float* g1  = (const float*)d_in[6];
    const float* be1 = (const float*)d_in[7];
    const float* W2l = (const float*)d_in[8];
    const float* b2l = (const float*)d_in[9];
    const float* W2r = (const float*)d_in[10];
    const float* g2  = (const float*)d_in[11];
    const float* be2 = (const float*)d_in[12];
    const float* Wm1 = (const float*)d_in[13];
    const float* bm1 = (const float*)d_in[14];
    const float* Wm2 = (const float*)d_in[15];
    const float* bm2 = (const float*)d_in[16];
    const float* Wm3 = (const float*)d_in[17];
    const float* bm3 = (const float*)d_in[18];
    float* out = (float*)d_out;

    float *pY, *pR, *pH, *pStats, *pAb, *pP, *pQ;
    int *pDeg, *pOff, *pFill, *pCsr;
    cudaGetSymbolAddress((void**)&pY, g_y);
    cudaGetSymbolAddress((void**)&pR, g_r);
    cudaGetSymbolAddress((void**)&pH, g_h);
    cudaGetSymbolAddress((void**)&pStats, g_stats);
    cudaGetSymbolAddress((void**)&pAb, g_ab);
    cudaGetSymbolAddress((void**)&pP, g_P);
    cudaGetSymbolAddress((void**)&pQ, g_Q);
    cudaGetSymbolAddress((void**)&pDeg, g_deg);
    cudaGetSymbolAddress((void**)&pOff, g_off);
    cudaGetSymbolAddress((void**)&pFill, g_fill);
    cudaGetSymbolAddress((void**)&pCsr, g_csr);

    const int smemGemm128 = (64 * 136 + 64 * 256) * 4;   // 100352 B
    const int smemGemm64  = (32 * 136 + 32 * 256) * 4;   // 50176 B
    const int smemEdge    = (64 * 264 + 64 * 128 + 16 * 128 + 128 + 64) * 4; // 109312 B
    cudaFuncSetAttribute(node_gemm<128>, cudaFuncAttributeMaxDynamicSharedMemorySize, smemGemm128);
    cudaFuncSetAttribute(node_gemm<64>,  cudaFuncAttributeMaxDynamicSharedMemorySize, smemGemm64);
    cudaFuncSetAttribute(edge_mlp_kernel, cudaFuncAttributeMaxDynamicSharedMemorySize, smemEdge);

    // ---- CSR build (dst identical for both layers) ----
    cudaMemsetAsync(pDeg, 0, NN * sizeof(int));
    cudaMemsetAsync(pFill, 0, NN * sizeof(int));
    cudaMemsetAsync(pStats, 0, 128 * sizeof(float));
    detect_idx_kernel<<<1, 1>>>(ei);
    hist_kernel<<<(EE + 255) / 256, 256>>>(ei, pDeg);
    scan_kernel<<<1, 1024>>>(pDeg, pOff);
    csr_fill_kernel<<<(EE + 255) / 256, 256>>>(ei, pOff, pFill, pCsr);

    // ---- layer 1 ----
    node_gemm<128><<<dim3(296, 1), 256, smemGemm128>>>(
        x, W1l, 128, W1r, 128, 64, pY, 64, nullptr, pR, 64, nullptr);
    aggregate_kernel<<<NN / 8, 256>>>(pOff, pCsr, pY, pR, b1l, pH, pStats);
    bn_param_kernel<<<1, 64>>>(pStats, g1, be1, pAb);

    // ---- layer 2 ----
    cudaMemsetAsync(pStats, 0, 128 * sizeof(float));
    node_gemm<64><<<dim3(296, 1), 256, smemGemm64>>>(
        pH, W2l, 64, W2r, 64, 64, pY, 64, nullptr, pR, 64, pAb);
    aggregate_kernel<<<NN / 8, 256>>>(pOff, pCsr, pY, pR, b2l, pH, pStats);
    bn_param_kernel<<<1, 64>>>(pStats, g2, be2, pAb + 128);

    // ---- node precompute for edge MLP: P (with bm1) and Q ----
    node_gemm<64><<<dim3(296, 2), 256, smemGemm64>>>(
        pH, Wm1, 144, Wm1 + 80, 144, 128, pP, 128, bm1, pQ, 128, pAb + 128);

    // ---- per-edge MLP ----
    edge_mlp_kernel<<<(EE + 127) / 128, 256, smemEdge>>>(
        ei, ea, pP, pQ, Wm1, Wm2, bm2, Wm3, bm3, out);
}

// round 3
// speedup vs baseline: 1.3325x; 1.3325x over previous
#include <cuda_runtime.h>
#include <math.h>

#define NN 50000
#define EE 800000

// ---------------- scratch (device globals; no allocations allowed) ----------
__device__ float g_y[NN * 64];      // messages y = h @ Wl^T
__device__ float g_r[NN * 64];      // root    r = h @ Wr^T
__device__ float g_h[NN * 64];      // pre-BN hidden
__device__ float g_stats[128];      // per-channel sum / sumsq
__device__ float g_ab[256];         // BN affine: [a1|c1|a2|c2]
__device__ float g_P[NN * 128];     // P = hf @ Wm1[:, :64]^T + bm1
__device__ float g_Q[NN * 128];     // Q = hf @ Wm1[:, 80:]^T
__device__ int   g_deg[NN];         // in-degree
__device__ int   g_off[NN + 1];     // CSR offsets
__device__ int   g_fill[NN];        // fill cursors
__device__ int   g_csr[EE];         // src node per CSR slot (grouped by dst)
__device__ int   g_idx64;           // 1 if edge_index is int64, 0 if int32

// ---------------- dtype detection for edge_index ---------------------------
__global__ void detect_idx_kernel(const void* ei) {
    const unsigned int* w = (const unsigned int*)ei;
    int f = 1;
    for (int i = 0; i < 32; i++)
        if (w[2 * i + 1] != 0u) f = 0;   // int32 data: odd words are random ids
    g_idx64 = f;
}

__device__ __forceinline__ int load_idx(const void* ei, long long i, int is64) {
    if (is64) return (int)__ldg(((const long long*)ei) + i);
    return __ldg(((const int*)ei) + i);
}

// ---------------- CSR build --------------------------------------------------
__global__ void hist_kernel(const void* __restrict__ ei, int* __restrict__ deg) {
    int e = blockIdx.x * blockDim.x + threadIdx.x;
    if (e >= EE) return;
    int dst = load_idx(ei, (long long)EE + e, g_idx64);
    atomicAdd(deg + dst, 1);
}

__global__ void scan_kernel(const int* __restrict__ deg, int* __restrict__ off) {
    __shared__ int part[1024];
    int tid = threadIdx.x;                 // 1024 threads, 1 block
    const int CH = (NN + 1023) / 1024;     // 49
    int s0 = tid * CH;
    int lsum = 0;
    for (int i = 0; i < CH; i++) {
        int idx = s0 + i;
        if (idx < NN) lsum += deg[idx];
    }
    part[tid] = lsum;
    __syncthreads();
    for (int d = 1; d < 1024; d <<= 1) {
        int v = (tid >= d) ? part[tid - d] : 0;
        __syncthreads();
        part[tid] += v;
        __syncthreads();
    }
    int run = (tid == 0) ? 0 : part[tid - 1];
    for (int i = 0; i < CH; i++) {
        int idx = s0 + i;
        if (idx < NN) { off[idx] = run; run += deg[idx]; }
    }
    if (tid == 1023) off[NN] = run;
}

__global__ void csr_fill_kernel(const void* __restrict__ ei,
                                const int* __restrict__ off,
                                int* __restrict__ fill,
                                int* __restrict__ csr) {
    int e = blockIdx.x * blockDim.x + threadIdx.x;
    if (e >= EE) return;
    int is64 = g_idx64;
    int src = load_idx(ei, e, is64);
    int dst = load_idx(ei, (long long)EE + e, is64);
    int slot = off[dst] + atomicAdd(fill + dst, 1);
    csr[slot] = src;
}

// ---------------- aggregate + finalize + BN stats (fused) --------------------
// h[n] = mean_{src->n} y[src] + bl + r[n]; stats <- per-channel sum/sumsq
__global__ void aggregate_kernel(const int* __restrict__ off,
                                 const int* __restrict__ csr,
                                 const float* __restrict__ y,
                                 const float* __restrict__ r,
                                 const float* __restrict__ bl,
                                 float* __restrict__ h,
                                 float* __restrict__ stats) {
    __shared__ float sbuf[128];
    int tid = threadIdx.x;
    int lane = tid & 31, wid = tid >> 5;
    if (tid < 128) sbuf[tid] = 0.f;
    __syncthreads();

    int n = blockIdx.x * 8 + wid;          // 8 warps = 8 nodes per block
    int beg = off[n], end = off[n + 1];
    float2 acc = make_float2(0.f, 0.f);
    for (int base = beg; base < end; base += 32) {
        int idx = base + lane;
        int s = (idx < end) ? __ldg(csr + idx) : 0;
        int m = min(32, end - base);
        for (int j = 0; j < m; j++) {
            int sj = __shfl_sync(0xffffffffu, s, j);
            float2 v = *(const float2*)(y + (size_t)sj * 64 + lane * 2);
            acc.x += v.x;
            acc.y += v.y;
        }
    }
    int c = lane * 2;
    float inv = 1.f / fmaxf((float)(end - beg), 1.f);
    float2 rv = *(const float2*)(r + (size_t)n * 64 + c);
    float h0 = acc.x * inv + __ldg(bl + c) + rv.x;
    float h1 = acc.y * inv + __ldg(bl + c + 1) + rv.y;
    *(float2*)(h + (size_t)n * 64 + c) = make_float2(h0, h1);
    atomicAdd(&sbuf[c], h0);
    atomicAdd(&sbuf[c + 1], h1);
    atomicAdd(&sbuf[64 + c], h0 * h0);
    atomicAdd(&sbuf[64 + c + 1], h1 * h1);
    __syncthreads();
    if (tid < 128) atomicAdd(stats + tid, sbuf[tid]);
}

// ---------------- BN params: a = g/sqrt(var+eps), c = beta - a*mu ------------
__global__ void bn_param_kernel(const float* __restrict__ stats,
                                const float* __restrict__ gamma,
                                const float* __restrict__ beta,
                                float* __restrict__ ab) {
    int c = threadIdx.x;  // 64 threads
    float mu = stats[c] * (1.f / (float)NN);
    float var = stats[64 + c] * (1.f / (float)NN) - mu * mu;
    float a = gamma[c] * rsqrtf(var + 1e-5f);
    ab[c] = a;
    ab[64 + c] = beta[c] - a * mu;
}

// ---------------- node GEMM: out[n, o] = sum_k A[n,k] * Brow(o)[k] ----------
// A: [NN, K]; output columns < split come from B1/out1 (optional bias1),
// otherwise B2/out2. Optional per-channel affine+ReLU applied to A on load.
template <int K>
__global__ void __launch_bounds__(256, 2) node_gemm(
    const float* __restrict__ A,
    const float* __restrict__ B1, int ldb1,
    const float* __restrict__ B2, int ldb2,
    int split,
    float* __restrict__ out1, int w1, const float* __restrict__ bias1,
    float* __restrict__ out2, int w2,
    const float* __restrict__ ab)
{
    extern __shared__ float sm[];
    float* As = sm;              // [K][68]  (k-major, padded)
    float* Bs = sm + K * 68;     // [K][128] (k-major)
    const int tid = threadIdx.x;
    const int colBase = blockIdx.y * 128;

    // stage B tile (once per block)
    {
        int o = tid & 127;
        int colg = colBase + o;
        const float* brow = (colg < split) ? (B1 + (size_t)colg * ldb1)
                                           : (B2 + (size_t)(colg - split) * ldb2);
        for (int k = (tid >> 7); k < K; k += 2)
            Bs[k * 128 + o] = __ldg(brow + k);
    }
    __syncthreads();

    const int tx = tid & 15;   // output group (8 cols)
    const int ty = tid >> 4;   // node group (4 rows)

    float binit[8];
#pragma unroll
    for (int j = 0; j < 8; j++) {
        int colg = colBase + tx * 8 + j;
        binit[j] = (bias1 != nullptr && colg < split) ? __ldg(bias1 + colg) : 0.f;
    }

    const int numTiles = (NN + 63) / 64;
    for (int nt = blockIdx.x; nt < numTiles; nt += gridDim.x) {
        int n0 = nt * 64;
        // stage A tile (transposed), optional fused BN+ReLU
        {
            int nl = tid >> 2;
            int n = n0 + nl;
            int kq = (tid & 3) * 4;
#pragma unroll
            for (int kb = kq; kb < K; kb += 16) {
                float4 v;
                if (n < NN) v = *(const float4*)(A + (size_t)n * K + kb);
                else        v = make_float4(0.f, 0.f, 0.f, 0.f);
                if (ab) {
                    v.x = fmaxf(ab[kb + 0] * v.x + ab[64 + kb + 0], 0.f);
                    v.y = fmaxf(ab[kb + 1] * v.y + ab[64 + kb + 1], 0.f);
                    v.z = fmaxf(ab[kb + 2] * v.z + ab[64 + kb + 2], 0.f);
                    v.w = fmaxf(ab[kb + 3] * v.w + ab[64 + kb + 3], 0.f);
                }
                As[(kb + 0) * 68 + nl] = v.x;
                As[(kb + 1) * 68 + nl] = v.y;
                As[(kb + 2) * 68 + nl] = v.z;
                As[(kb + 3) * 68 + nl] = v.w;
            }
        }
        __syncthreads();

        float acc[4][8];
#pragma unroll
        for (int i = 0; i < 4; i++)
#pragma unroll
            for (int j = 0; j < 8; j++) acc[i][j] = binit[j];

#pragma unroll 4
        for (int k = 0; k < K; k++) {
            float4 a4 = *(const float4*)(As + k * 68 + ty * 4);
            float4 b0 = *(const float4*)(Bs + k * 128 + tx * 8);
            float4 b1 = *(const float4*)(Bs + k * 128 + tx * 8 + 4);
            float av[4] = {a4.x, a4.y, a4.z, a4.w};
            float bv[8] = {b0.x, b0.y, b0.z, b0.w, b1.x, b1.y, b1.z, b1.w};
#pragma unroll
            for (int i = 0; i < 4; i++)
#pragma unroll
                for (int j = 0; j < 8; j++) acc[i][j] += av[i] * bv[j];
        }
        __syncthreads();

        int colg0 = colBase + tx * 8;
#pragma unroll
        for (int i = 0; i < 4; i++) {
            int n = n0 + ty * 4 + i;
            if (n < NN) {
                float4 v0 = make_float4(acc[i][0], acc[i][1], acc[i][2], acc[i][3]);
                float4 v1 = make_float4(acc[i][4], acc[i][5], acc[i][6], acc[i][7]);
                if (colg0 < split) {
                    *(float4*)(out1 + (size_t)n * w1 + colg0) = v0;
                    *(float4*)(out1 + (size_t)n * w1 + colg0 + 4) = v1;
                } else {
                    *(float4*)(out2 + (size_t)n * w2 + colg0 - split) = v0;
                    *(float4*)(out2 + (size_t)n * w2 + colg0 - split + 4) = v1;
                }
            }
        }
    }
}

// ---------------- per-edge MLP ----------------------------------------------
// z1 = relu(P[src] + Q[dst] + ea @ Wm1e^T)     (P already carries bm1)
// z2 = relu(z1 @ Wm2^T + bm2);  out = z2 @ Wm3^T + bm3
__global__ void __launch_bounds__(256, 2) edge_mlp_kernel(
    const void* __restrict__ ei, const float* __restrict__ ea,
    const float* __restrict__ P, const float* __restrict__ Q,
    const float* __restrict__ Wm1, const float* __restrict__ Wm2,
    const float* __restrict__ bm2, const float* __restrict__ Wm3,
    const float* __restrict__ bm3, float* __restrict__ out)
{
    extern __shared__ float sm[];
    float* z1s  = sm;                 // [e:128][k:132 pad]
    float* w2s  = z1s + 128 * 132;    // [k:128][o:64]
    float* w1es = w2s + 128 * 64;     // [k:16][j:128]
    float* w3s  = w1es + 16 * 128;    // [c:64][2]
    float* bm2s = w3s + 128;          // [64]
    int tid = threadIdx.x;
    int is64 = g_idx64;

    for (int i = tid; i < 64 * 128; i += 256) {
        int o = i >> 7, k = i & 127;
        w2s[k * 64 + o] = __ldg(Wm2 + o * 128 + k);
    }
    for (int i = tid; i < 16 * 128; i += 256) {
        int j = i >> 4, k = i & 15;
        w1es[k * 128 + j] = __ldg(Wm1 + j * 144 + 64 + k);
    }
    if (tid < 128) { int c2 = tid >> 1, t = tid & 1; w3s[tid] = __ldg(Wm3 + t * 64 + c2); }
    if (tid < 64) bm2s[tid] = __ldg(bm2 + tid);
    __syncthreads();

    // ---- phase A: build z1 tile (one warp per edge) ----
    int warp = tid >> 5, lane = tid & 31;
    int e0 = blockIdx.x * 128;
    for (int el = warp; el < 128; el += 8) {
        int e = e0 + el;
        float4 acc = make_float4(0.f, 0.f, 0.f, 0.f);
        if (e < EE) {
            int src = load_idx(ei, e, is64);
            int dst = load_idx(ei, (long long)EE + e, is64);
            float4 p = *(const float4*)(P + (size_t)src * 128 + lane * 4);
            float4 q = *(const float4*)(Q + (size_t)dst * 128 + lane * 4);
            acc.x = p.x + q.x; acc.y = p.y + q.y;
            acc.z = p.z + q.z; acc.w = p.w + q.w;
            float v = (lane < 16) ? __ldg(ea + (size_t)e * 16 + lane) : 0.f;
#pragma unroll
            for (int k = 0; k < 16; k++) {
                float sc = __shfl_sync(0xffffffffu, v, k);
                float4 wv = *(const float4*)(w1es + k * 128 + lane * 4);
                acc.x += sc * wv.x; acc.y += sc * wv.y;
                acc.z += sc * wv.z; acc.w += sc * wv.w;
            }
            acc.x = fmaxf(acc.x, 0.f); acc.y = fmaxf(acc.y, 0.f);
            acc.z = fmaxf(acc.z, 0.f); acc.w = fmaxf(acc.w, 0.f);
        }
        *(float4*)(z1s + el * 132 + lane * 4) = acc;
    }
    __syncthreads();

    // ---- phase B: GEMM2, 128 edges x 64 outs, reg tile 4x8 ----
    int og = tid & 7;    // 8 output groups of 8
    int eg = tid >> 3;   // 32 edge groups of 4
    float acc2[4][8];
#pragma unroll
    for (int i = 0; i < 4; i++)
#pragma unroll
        for (int j = 0; j < 8; j++) acc2[i][j] = 0.f;

    const float* zb = z1s + eg * 4 * 132;
#pragma unroll 4
    for (int k = 0; k < 128; k++) {
        float a0 = zb[k];
        float a1 = zb[132 + k];
        float a2 = zb[264 + k];
        float a3 = zb[396 + k];
        float4 b0 = *(const float4*)(w2s + k * 64 + og * 8);
        float4 b1 = *(const float4*)(w2s + k * 64 + og * 8 + 4);
        float av[4] = {a0, a1, a2, a3};
        float bv[8] = {b0.x, b0.y, b0.z, b0.w, b1.x, b1.y, b1.z, b1.w};
#pragma unroll
        for (int i = 0; i < 4; i++)
#pragma unroll
            for (int j = 0; j < 8; j++) acc2[i][j] += av[i] * bv[j];
    }

    // ---- phase C: bias + relu + layer3 partial dot, reduce over 8 lanes ----
    float o0[4] = {0.f, 0.f, 0.f, 0.f};
    float o1[4] = {0.f, 0.f, 0.f, 0.f};
#pragma unroll
    for (int j = 0; j < 8; j++) {
        int ch = og * 8 + j;
        float w30 = w3s[ch * 2], w31 = w3s[ch * 2 + 1], bb = bm2s[ch];
#pragma unroll
        for (int i = 0; i < 4; i++) {
            float z = fmaxf(acc2[i][j] + bb, 0.f);
            o0[i] += z * w30;
            o1[i] += z * w31;
        }
    }
#pragma unroll
    for (int i = 0; i < 4; i++) {
#pragma unroll
        for (int off = 4; off > 0; off >>= 1) {
            o0[i] += __shfl_down_sync(0xffffffffu, o0[i], off, 8);
            o1[i] += __shfl_down_sync(0xffffffffu, o1[i], off, 8);
        }
    }
    if (og == 0) {
        float b30 = __ldg(bm3), b31 = __ldg(bm3 + 1);
#pragma unroll
        for (int i = 0; i < 4; i++) {
            int e = e0 + eg * 4 + i;
            if (e < EE) {
                float2 rv;
                rv.x = o0[i] + b30;
                rv.y = o1[i] + b31;
                *(float2*)(out + (size_t)e * 2) = rv;
            }
        }
    }
}

// ---------------- host orchestration ----------------------------------------
extern "C" void kernel_launch(void* const* d_in, const int* in_sizes, int n_in,
                              void* d_out, int out_size)
{
    (void)in_sizes; (void)n_in; (void)out_size;
    const float* x   = (const float*)d_in[0];
    const void*  ei  = d_in[1];
    const float* ea  = (const float*)d_in[2];
    const float* W1l = (const float*)d_in[3];
    const float* b1l = (const float*)d_in[4];
    const float* W1r = (const float*)d_in[5];
    const float* g1  = (const float*)d_in[6];
    const float* be1 = (const float*)d_in[7];
    const float* W2l = (const float*)d_in[8];
    const float* b2l = (const float*)d_in[9];
    const float* W2r = (const float*)d_in[10];
    const float* g2  = (const float*)d_in[11];
    const float* be2 = (const float*)d_in[12];
    const float* Wm1 = (const float*)d_in[13];
    const float* bm1 = (const float*)d_in[14];
    const float* Wm2 = (const float*)d_in[15];
    const float* bm2 = (const float*)d_in[16];
    const float* Wm3 = (const float*)d_in[17];
    const float* bm3 = (const float*)d_in[18];
    float* out = (float*)d_out;

    float *pY, *pR, *pH, *pStats, *pAb, *pP, *pQ;
    int *pDeg, *pOff, *pFill, *pCsr;
    cudaGetSymbolAddress((void**)&pY, g_y);
    cudaGetSymbolAddress((void**)&pR, g_r);
    cudaGetSymbolAddress((void**)&pH, g_h);
    cudaGetSymbolAddress((void**)&pStats, g_stats);
    cudaGetSymbolAddress((void**)&pAb, g_ab);
    cudaGetSymbolAddress((void**)&pP, g_P);
    cudaGetSymbolAddress((void**)&pQ, g_Q);
    cudaGetSymbolAddress((void**)&pDeg, g_deg);
    cudaGetSymbolAddress((void**)&pOff, g_off);
    cudaGetSymbolAddress((void**)&pFill, g_fill);
    cudaGetSymbolAddress((void**)&pCsr, g_csr);

    const int smemGemm128 = (128 * 68 + 128 * 128) * 4;   // 100352 B
    const int smemGemm64  = (64 * 68 + 64 * 128) * 4;     // 50176 B
    const int smemEdge    = (128 * 132 + 128 * 64 + 16 * 128 + 128 + 64) * 4; // 109312 B
    cudaFuncSetAttribute(node_gemm<128>, cudaFuncAttributeMaxDynamicSharedMemorySize, smemGemm128);
    cudaFuncSetAttribute(node_gemm<64>,  cudaFuncAttributeMaxDynamicSharedMemorySize, smemGemm64);
    cudaFuncSetAttribute(edge_mlp_kernel, cudaFuncAttributeMaxDynamicSharedMemorySize, smemEdge);

    // ---- CSR build (dst identical for both layers) ----
    cudaMemsetAsync(pDeg, 0, NN * sizeof(int));
    cudaMemsetAsync(pFill, 0, NN * sizeof(int));
    cudaMemsetAsync(pStats, 0, 128 * sizeof(float));
    detect_idx_kernel<<<1, 1>>>(ei);
    hist_kernel<<<(EE + 255) / 256, 256>>>(ei, pDeg);
    scan_kernel<<<1, 1024>>>(pDeg, pOff);
    csr_fill_kernel<<<(EE + 255) / 256, 256>>>(ei, pOff, pFill, pCsr);

    // ---- layer 1 ----
    node_gemm<128><<<dim3(296, 1), 256, smemGemm128>>>(
        x, W1l, 128, W1r, 128, 64, pY, 64, nullptr, pR, 64, nullptr);
    aggregate_kernel<<<NN / 8, 256>>>(pOff, pCsr, pY, pR, b1l, pH, pStats);
    bn_param_kernel<<<1, 64>>>(pStats, g1, be1, pAb);

    // ---- layer 2 ----
    cudaMemsetAsync(pStats, 0, 128 * sizeof(float));
    node_gemm<64><<<dim3(296, 1), 256, smemGemm64>>>(
        pH, W2l, 64, W2r, 64, 64, pY, 64, nullptr, pR, 64, pAb);
    aggregate_kernel<<<NN / 8, 256>>>(pOff, pCsr, pY, pR, b2l, pH, pStats);
    bn_param_kernel<<<1, 64>>>(pStats, g2, be2, pAb + 128);

    // ---- node precompute for edge MLP: P (with bm1) and Q ----
    node_gemm<64><<<dim3(296, 2), 256, smemGemm64>>>(
        pH, Wm1, 144, Wm1 + 80, 144, 128, pP, 128, bm1, pQ, 128, pAb + 128);

    // ---- per-edge MLP ----
    edge_mlp_kernel<<<(EE + 127) / 128, 256, smemEdge>>>(
        ei, ea, pP, pQ, Wm1, Wm2, bm2, Wm3, bm3, out);
}